// round 5
// baseline (speedup 1.0000x reference)
#include <cuda_runtime.h>

#define NB 8
#define NS 2048
#define ND 768
#define NH 64
#define SK 68          // padded smem row stride (floats); 68*4B = 272B, 16B-aligned

__device__ float g_Q[NB * NS * NH];
__device__ float g_K[NB * NS * NH];
__device__ float g_V[NB * NS * NH];

// ---------------------------------------------------------------------------
// Kernel 1: QKV projection. [16384,768] x [768,64] per z-slice.
// 64x64x16 tiles, 256 threads, 4x4 microtiles, all-float4 smem reads.
// ---------------------------------------------------------------------------
__global__ __launch_bounds__(256, 2) void proj_kernel(
    const float* __restrict__ X,
    const float* __restrict__ Wq,
    const float* __restrict__ Wk,
    const float* __restrict__ Wv)
{
    const int z = blockIdx.z;
    const float* __restrict__ W   = (z == 0) ? Wq : (z == 1) ? Wk : Wv;
    float* __restrict__       Out = (z == 0) ? g_Q : (z == 1) ? g_K : g_V;

    __shared__ float As[16][64];   // [k][row] (transposed X tile)
    __shared__ float Bs[16][64];   // [k][col]

    const int row0 = blockIdx.x * 64;
    const int tid  = threadIdx.x;
    const int tx   = tid & 15;
    const int ty   = tid >> 4;

    const int lr  = tid >> 2;
    const int lk4 = (tid & 3) * 4;
    const int wk  = tid >> 4;
    const int wc  = (tid & 15) * 4;

    float acc[4][4];
#pragma unroll
    for (int i = 0; i < 4; ++i)
#pragma unroll
        for (int j = 0; j < 4; ++j) acc[i][j] = 0.0f;

    for (int kk = 0; kk < ND; kk += 16) {
        {
            float4 xa = *reinterpret_cast<const float4*>(
                X + (size_t)(row0 + lr) * ND + kk + lk4);
            As[lk4 + 0][lr] = xa.x;
            As[lk4 + 1][lr] = xa.y;
            As[lk4 + 2][lr] = xa.z;
            As[lk4 + 3][lr] = xa.w;
        }
        {
            *reinterpret_cast<float4*>(&Bs[wk][wc]) =
                *reinterpret_cast<const float4*>(W + (size_t)(kk + wk) * NH + wc);
        }
        __syncthreads();

#pragma unroll
        for (int k = 0; k < 16; ++k) {
            float4 av = *reinterpret_cast<const float4*>(&As[k][ty * 4]);
            float4 bv = *reinterpret_cast<const float4*>(&Bs[k][tx * 4]);
            acc[0][0] = fmaf(av.x, bv.x, acc[0][0]);
            acc[0][1] = fmaf(av.x, bv.y, acc[0][1]);
            acc[0][2] = fmaf(av.x, bv.z, acc[0][2]);
            acc[0][3] = fmaf(av.x, bv.w, acc[0][3]);
            acc[1][0] = fmaf(av.y, bv.x, acc[1][0]);
            acc[1][1] = fmaf(av.y, bv.y, acc[1][1]);
            acc[1][2] = fmaf(av.y, bv.z, acc[1][2]);
            acc[1][3] = fmaf(av.y, bv.w, acc[1][3]);
            acc[2][0] = fmaf(av.z, bv.x, acc[2][0]);
            acc[2][1] = fmaf(av.z, bv.y, acc[2][1]);
            acc[2][2] = fmaf(av.z, bv.z, acc[2][2]);
            acc[2][3] = fmaf(av.z, bv.w, acc[2][3]);
            acc[3][0] = fmaf(av.w, bv.x, acc[3][0]);
            acc[3][1] = fmaf(av.w, bv.y, acc[3][1]);
            acc[3][2] = fmaf(av.w, bv.z, acc[3][2]);
            acc[3][3] = fmaf(av.w, bv.w, acc[3][3]);
        }
        __syncthreads();
    }

#pragma unroll
    for (int i = 0; i < 4; ++i) {
        float4 r = make_float4(acc[i][0], acc[i][1], acc[i][2], acc[i][3]);
        *reinterpret_cast<float4*>(
            Out + (size_t)(row0 + ty * 4 + i) * NH + tx * 4) = r;
    }
}

// ---------------------------------------------------------------------------
// Kernel 2: causal flash attention, GEMM-style register blocking.
// Block = 64 queries, 256 threads. Each thread owns a 4x4 microtile of the
// 64x64 score tile S and a 4x4 microtile of the 64x64 output O.
//   S = Q K^T : Qs[d][q], Ks[d][k] in smem (d-major), 16 FMA / 2 LDS.128.
//   softmax   : row state (m) reduced across the 16-lane tx-group via shfl;
//               l kept as per-thread partial, reduced once at the end.
//   O += P V  : P written transposed into the K buffer (aliased), Vs natural.
// Reversed block order: long (high-q) tiles first for causal load balance.
// ---------------------------------------------------------------------------
__global__ __launch_bounds__(256, 2) void attn_kernel(float* __restrict__ out)
{
    extern __shared__ float sm[];
    float* __restrict__ Qs = sm;                // [64][SK]  Q, d-major
    float* __restrict__ KP = sm + 64 * SK;      // [64][SK]  K (d-major) / P (k-major)
    float* __restrict__ Vs = sm + 2 * 64 * SK;  // [64][SK]  V, natural

    const int b   = blockIdx.y;
    const int qt  = (gridDim.x - 1) - blockIdx.x;
    const int q0  = qt * 64;
    const int tid = threadIdx.x;
    const int tx  = tid & 15;
    const int ty  = tid >> 4;

    const float* __restrict__ Qb = g_Q + (size_t)b * NS * NH;
    const float* __restrict__ Kb = g_K + (size_t)b * NS * NH;
    const float* __restrict__ Vb = g_V + (size_t)b * NS * NH;

    // Load Q tile once, transposed -> Qs[d][q]
    {
        const int r  = tid >> 2;
        const int dg = (tid & 3) * 16;
        const float4* qp = reinterpret_cast<const float4*>(Qb + (size_t)(q0 + r) * NH + dg);
#pragma unroll
        for (int u = 0; u < 4; ++u) {
            float4 v = qp[u];
            const int d = dg + u * 4;
            Qs[(d + 0) * SK + r] = v.x;
            Qs[(d + 1) * SK + r] = v.y;
            Qs[(d + 2) * SK + r] = v.z;
            Qs[(d + 3) * SK + r] = v.w;
        }
    }

    float o[4][4];
#pragma unroll
    for (int i = 0; i < 4; ++i)
#pragma unroll
        for (int j = 0; j < 4; ++j) o[i][j] = 0.0f;
    float m[4] = {-1e30f, -1e30f, -1e30f, -1e30f};
    float l[4] = {0.f, 0.f, 0.f, 0.f};

    for (int t = 0; t <= qt; ++t) {
        const int k0 = t * 64;

        __syncthreads();   // previous iteration done reading KP(P) and Vs
        // Load K transposed -> KP[d][k], V natural -> Vs[k][h]
        {
            const int r  = tid >> 2;
            const int dg = (tid & 3) * 16;
            const float4* kp = reinterpret_cast<const float4*>(Kb + (size_t)(k0 + r) * NH + dg);
            const float4* vp = reinterpret_cast<const float4*>(Vb + (size_t)(k0 + r) * NH + dg);
#pragma unroll
            for (int u = 0; u < 4; ++u) {
                float4 kv = kp[u];
                const int d = dg + u * 4;
                KP[(d + 0) * SK + r] = kv.x;
                KP[(d + 1) * SK + r] = kv.y;
                KP[(d + 2) * SK + r] = kv.z;
                KP[(d + 3) * SK + r] = kv.w;
                *reinterpret_cast<float4*>(&Vs[r * SK + dg + u * 4]) = vp[u];
            }
        }
        __syncthreads();

        // ---- S = Q K^T (64x64x64, this thread: rows ty*4.., cols tx*4..) ----
        float s[4][4];
#pragma unroll
        for (int i = 0; i < 4; ++i)
#pragma unroll
            for (int j = 0; j < 4; ++j) s[i][j] = 0.0f;

#pragma unroll 4
        for (int d = 0; d < 64; ++d) {
            float4 qv = *reinterpret_cast<const float4*>(&Qs[d * SK + ty * 4]);
            float4 kv = *reinterpret_cast<const float4*>(&KP[d * SK + tx * 4]);
            s[0][0] = fmaf(qv.x, kv.x, s[0][0]);
            s[0][1] = fmaf(qv.x, kv.y, s[0][1]);
            s[0][2] = fmaf(qv.x, kv.z, s[0][2]);
            s[0][3] = fmaf(qv.x, kv.w, s[0][3]);
            s[1][0] = fmaf(qv.y, kv.x, s[1][0]);
            s[1][1] = fmaf(qv.y, kv.y, s[1][1]);
            s[1][2] = fmaf(qv.y, kv.z, s[1][2]);
            s[1][3] = fmaf(qv.y, kv.w, s[1][3]);
            s[2][0] = fmaf(qv.z, kv.x, s[2][0]);
            s[2][1] = fmaf(qv.z, kv.y, s[2][1]);
            s[2][2] = fmaf(qv.z, kv.z, s[2][2]);
            s[2][3] = fmaf(qv.z, kv.w, s[2][3]);
            s[3][0] = fmaf(qv.w, kv.x, s[3][0]);
            s[3][1] = fmaf(qv.w, kv.y, s[3][1]);
            s[3][2] = fmaf(qv.w, kv.z, s[3][2]);
            s[3][3] = fmaf(qv.w, kv.w, s[3][3]);
        }

        // scale; causal mask only on the diagonal tile
#pragma unroll
        for (int i = 0; i < 4; ++i)
#pragma unroll
            for (int j = 0; j < 4; ++j) s[i][j] *= 0.125f;
        if (t == qt) {
#pragma unroll
            for (int i = 0; i < 4; ++i)
#pragma unroll
                for (int j = 0; j < 4; ++j)
                    if (tx * 4 + j > ty * 4 + i) s[i][j] = -1e30f;
        }

        // ---- online softmax: row max over the 16-lane tx-group ----
        float rm[4];
#pragma unroll
        for (int i = 0; i < 4; ++i)
            rm[i] = fmaxf(fmaxf(s[i][0], s[i][1]), fmaxf(s[i][2], s[i][3]));
#pragma unroll
        for (int off = 8; off >= 1; off >>= 1) {
#pragma unroll
            for (int i = 0; i < 4; ++i)
                rm[i] = fmaxf(rm[i], __shfl_xor_sync(0xffffffffu, rm[i], off));
        }

        float corr[4];
#pragma unroll
        for (int i = 0; i < 4; ++i) {
            float mn = fmaxf(m[i], rm[i]);
            corr[i]  = __expf(m[i] - mn);   // 0 on first tile (m = -1e30)
            m[i]     = mn;
        }
#pragma unroll
        for (int i = 0; i < 4; ++i) {
            l[i] *= corr[i];
            o[i][0] *= corr[i]; o[i][1] *= corr[i];
            o[i][2] *= corr[i]; o[i][3] *= corr[i];
        }
#pragma unroll
        for (int i = 0; i < 4; ++i) {
#pragma unroll
            for (int j = 0; j < 4; ++j)
                s[i][j] = __expf(s[i][j] - m[i]);   // masked -> exp(-1e30) = 0
            l[i] += s[i][0] + s[i][1] + s[i][2] + s[i][3];
        }

        __syncthreads();   // all warps done reading KP as Ks
        // write P transposed into KP: KP[k][q], float4 along q
#pragma unroll
        for (int j = 0; j < 4; ++j) {
            *reinterpret_cast<float4*>(&KP[(tx * 4 + j) * SK + ty * 4]) =
                make_float4(s[0][j], s[1][j], s[2][j], s[3][j]);
        }
        __syncthreads();

        // ---- O += P V (64x64x64, this thread: rows ty*4.., cols tx*4..) ----
#pragma unroll 4
        for (int k = 0; k < 64; ++k) {
            float4 pv = *reinterpret_cast<const float4*>(&KP[k * SK + ty * 4]);
            float4 vv = *reinterpret_cast<const float4*>(&Vs[k * SK + tx * 4]);
            o[0][0] = fmaf(pv.x, vv.x, o[0][0]);
            o[0][1] = fmaf(pv.x, vv.y, o[0][1]);
            o[0][2] = fmaf(pv.x, vv.z, o[0][2]);
            o[0][3] = fmaf(pv.x, vv.w, o[0][3]);
            o[1][0] = fmaf(pv.y, vv.x, o[1][0]);
            o[1][1] = fmaf(pv.y, vv.y, o[1][1]);
            o[1][2] = fmaf(pv.y, vv.z, o[1][2]);
            o[1][3] = fmaf(pv.y, vv.w, o[1][3]);
            o[2][0] = fmaf(pv.z, vv.x, o[2][0]);
            o[2][1] = fmaf(pv.z, vv.y, o[2][1]);
            o[2][2] = fmaf(pv.z, vv.z, o[2][2]);
            o[2][3] = fmaf(pv.z, vv.w, o[2][3]);
            o[3][0] = fmaf(pv.w, vv.x, o[3][0]);
            o[3][1] = fmaf(pv.w, vv.y, o[3][1]);
            o[3][2] = fmaf(pv.w, vv.z, o[3][2]);
            o[3][3] = fmaf(pv.w, vv.w, o[3][3]);
        }
    }

    // finalize: reduce per-thread partial l across the tx-group, normalize, store
#pragma unroll
    for (int off = 8; off >= 1; off >>= 1) {
#pragma unroll
        for (int i = 0; i < 4; ++i)
            l[i] += __shfl_xor_sync(0xffffffffu, l[i], off);
    }

    float* op = out + ((size_t)b * NS + q0) * NH;
#pragma unroll
    for (int i = 0; i < 4; ++i) {
        float inv = 1.0f / l[i];
        float4 r = make_float4(o[i][0] * inv, o[i][1] * inv,
                               o[i][2] * inv, o[i][3] * inv);
        *reinterpret_cast<float4*>(op + (size_t)(ty * 4 + i) * NH + tx * 4) = r;
    }
}

// ---------------------------------------------------------------------------
extern "C" void kernel_launch(void* const* d_in, const int* in_sizes, int n_in,
                              void* d_out, int out_size)
{
    const float* X  = (const float*)d_in[0];
    const float* Wq = (const float*)d_in[1];
    const float* Wk = (const float*)d_in[2];
    const float* Wv = (const float*)d_in[3];
    float* out = (float*)d_out;

    const int attn_smem = 3 * 64 * SK * (int)sizeof(float);   // 52224 B
    cudaFuncSetAttribute(attn_kernel,
                         cudaFuncAttributeMaxDynamicSharedMemorySize, attn_smem);

    proj_kernel<<<dim3((NB * NS) / 64, 1, 3), 256>>>(X, Wq, Wk, Wv);
    attn_kernel<<<dim3(NS / 64, NB), 256, attn_smem>>>(out);
}

// round 6
// speedup vs baseline: 3.4299x; 3.4299x over previous
#include <cuda_runtime.h>

#define NB 8
#define NS 2048
#define ND 768
#define NH 64

__device__ float g_Q[NB * NS * NH];
__device__ float g_K[NB * NS * NH];
__device__ float g_V[NB * NS * NH];

// ---------------------------------------------------------------------------
// TF32 helpers
// ---------------------------------------------------------------------------
__device__ __forceinline__ unsigned f2tf(float f) {
    unsigned u;
    asm("cvt.rna.tf32.f32 %0, %1;" : "=r"(u) : "f"(f));
    return u;
}
__device__ __forceinline__ uint4 f4tf(float4 v) {
    uint4 r;
    r.x = f2tf(v.x); r.y = f2tf(v.y); r.z = f2tf(v.z); r.w = f2tf(v.w);
    return r;
}
// C += A(16x8 row) * B(8x8 col), tf32 inputs, f32 accum
__device__ __forceinline__ void mma8(float c[4],
                                     unsigned a0, unsigned a1, unsigned a2, unsigned a3,
                                     unsigned b0, unsigned b1) {
    asm("mma.sync.aligned.m16n8k8.row.col.f32.tf32.tf32.f32 "
        "{%0,%1,%2,%3}, {%4,%5,%6,%7}, {%8,%9}, {%0,%1,%2,%3};"
        : "+f"(c[0]), "+f"(c[1]), "+f"(c[2]), "+f"(c[3])
        : "r"(a0), "r"(a1), "r"(a2), "r"(a3), "r"(b0), "r"(b1));
}

// ---------------------------------------------------------------------------
// Kernel 1: QKV projection via tf32 mma. [16384,768] x [768,64], 3 slices.
// Block: 128 threads (4 warps), tile 128m x 64n, k-stage 32.
// Warp w: rows [w*32, w*32+32) = 2 m16 tiles x 8 n8 tiles (64 accum regs).
// Xs stride 36 (=4 mod 32): A-frag gather g*4+t conflict-free.
// Ws stride 72 (=8 mod 32): B-frag gather t*8+g conflict-free.
// ---------------------------------------------------------------------------
#define XS_S 36
#define WS_S 72

__global__ __launch_bounds__(128, 3) void proj_kernel(
    const float* __restrict__ X,
    const float* __restrict__ Wq,
    const float* __restrict__ Wk,
    const float* __restrict__ Wv)
{
    const int z = blockIdx.z;
    const float* __restrict__ W   = (z == 0) ? Wq : (z == 1) ? Wk : Wv;
    float* __restrict__       Out = (z == 0) ? g_Q : (z == 1) ? g_K : g_V;

    __shared__ float Xs[128 * XS_S];
    __shared__ float Ws[32 * WS_S];

    const int row0 = blockIdx.x * 128;
    const int tid  = threadIdx.x;
    const int wrp  = tid >> 5;
    const int lane = tid & 31;
    const int g    = lane >> 2;
    const int t    = lane & 3;
    const int mrow = wrp * 32;

    float acc[2][8][4];
#pragma unroll
    for (int mt = 0; mt < 2; ++mt)
#pragma unroll
        for (int nt = 0; nt < 8; ++nt)
#pragma unroll
            for (int r = 0; r < 4; ++r) acc[mt][nt][r] = 0.0f;

    const int xr = tid >> 3;            // 0..15
    const int xc = (tid & 7) * 4;       // 0..28
    const int wr = tid >> 4;            // 0..7
    const int wc = (tid & 15) * 4;      // 0..60

    for (int kk = 0; kk < ND; kk += 32) {
        // load X tile 128x32 (tf32-rounded)
#pragma unroll
        for (int it = 0; it < 8; ++it) {
            const int r = xr + it * 16;
            float4 v = *reinterpret_cast<const float4*>(
                X + (size_t)(row0 + r) * ND + kk + xc);
            *reinterpret_cast<uint4*>(&Xs[r * XS_S + xc]) = f4tf(v);
        }
        // load W tile 32x64 (tf32-rounded)
#pragma unroll
        for (int it = 0; it < 4; ++it) {
            const int r = wr + it * 8;
            float4 v = *reinterpret_cast<const float4*>(
                W + (size_t)(kk + r) * NH + wc);
            *reinterpret_cast<uint4*>(&Ws[r * WS_S + wc]) = f4tf(v);
        }
        __syncthreads();

#pragma unroll
        for (int dc = 0; dc < 4; ++dc) {
            unsigned a[2][4];
#pragma unroll
            for (int mt = 0; mt < 2; ++mt) {
                const int rb = mrow + mt * 16;
                a[mt][0] = __float_as_uint(Xs[(rb + g)     * XS_S + dc * 8 + t]);
                a[mt][1] = __float_as_uint(Xs[(rb + g + 8) * XS_S + dc * 8 + t]);
                a[mt][2] = __float_as_uint(Xs[(rb + g)     * XS_S + dc * 8 + t + 4]);
                a[mt][3] = __float_as_uint(Xs[(rb + g + 8) * XS_S + dc * 8 + t + 4]);
            }
#pragma unroll
            for (int nt = 0; nt < 8; ++nt) {
                unsigned b0 = __float_as_uint(Ws[(dc * 8 + t)     * WS_S + nt * 8 + g]);
                unsigned b1 = __float_as_uint(Ws[(dc * 8 + t + 4) * WS_S + nt * 8 + g]);
                mma8(acc[0][nt], a[0][0], a[0][1], a[0][2], a[0][3], b0, b1);
                mma8(acc[1][nt], a[1][0], a[1][1], a[1][2], a[1][3], b0, b1);
            }
        }
        __syncthreads();
    }

#pragma unroll
    for (int mt = 0; mt < 2; ++mt) {
        const int rb = row0 + mrow + mt * 16;
#pragma unroll
        for (int nt = 0; nt < 8; ++nt) {
            *reinterpret_cast<float2*>(
                Out + (size_t)(rb + g) * NH + nt * 8 + 2 * t) =
                make_float2(acc[mt][nt][0], acc[mt][nt][1]);
            *reinterpret_cast<float2*>(
                Out + (size_t)(rb + g + 8) * NH + nt * 8 + 2 * t) =
                make_float2(acc[mt][nt][2], acc[mt][nt][3]);
        }
    }
}

// ---------------------------------------------------------------------------
// Kernel 2: causal flash attention via tf32 mma.
// Block: 128 threads (4 warps), 64 q-tile; warp w owns q rows [w*16, w*16+16).
// Per k-tile of 64 keys:
//   S = Q K^T : 8 n-tiles x 8 d-chunks of m16n8k8 mma (Q,K tf32 in smem).
//   softmax   : rows live in C-frag (rows g, g+8 per thread); quad-shuffle max.
//   P -> smem (warp-private rows, __syncwarp only), re-fragment as A.
//   O += P V  : V natural layout is exactly the B-fragment layout.
// Strides: Qs/Ks/Ps 68 (=4 mod 32), Vs 72 (=8 mod 32) -> all fragment
// gathers conflict-free.
// ---------------------------------------------------------------------------
#define QS_S 68
#define KS_S 68
#define PS_S 68
#define VS_S 72

__global__ __launch_bounds__(128, 2) void attn_kernel(float* __restrict__ out)
{
    extern __shared__ float sm[];
    float* __restrict__ Qs = sm;                                  // 64 x 68
    float* __restrict__ Ks = Qs + 64 * QS_S;                      // 64 x 68
    float* __restrict__ Ps = Ks + 64 * KS_S;                      // 64 x 68
    float* __restrict__ Vs = Ps + 64 * PS_S;                      // 64 x 72

    const int b    = blockIdx.y;
    const int qt   = (gridDim.x - 1) - blockIdx.x;   // long tiles first
    const int q0   = qt * 64;
    const int tid  = threadIdx.x;
    const int wrp  = tid >> 5;
    const int lane = tid & 31;
    const int g    = lane >> 2;
    const int t    = lane & 3;
    const int w16  = wrp * 16;

    const float* __restrict__ Qb = g_Q + (size_t)b * NS * NH;
    const float* __restrict__ Kb = g_K + (size_t)b * NS * NH;
    const float* __restrict__ Vb = g_V + (size_t)b * NS * NH;

    // Q tile -> smem (tf32-rounded). 2 threads per row.
    {
        const int r = tid >> 1;
        const int c = (tid & 1) * 32;
        const float4* qp = reinterpret_cast<const float4*>(
            Qb + (size_t)(q0 + r) * NH + c);
#pragma unroll
        for (int u = 0; u < 8; ++u)
            *reinterpret_cast<uint4*>(&Qs[r * QS_S + c + u * 4]) = f4tf(qp[u]);
    }

    float o[8][4];
#pragma unroll
    for (int nt = 0; nt < 8; ++nt)
#pragma unroll
        for (int r = 0; r < 4; ++r) o[nt][r] = 0.0f;
    float mA = -1e30f, mB = -1e30f;
    float lA = 0.0f,   lB = 0.0f;

    for (int kt = 0; kt <= qt; ++kt) {
        const int k0 = kt * 64;

        __syncthreads();   // prev iter done reading Ks/Vs
        {
            const int r = tid >> 1;
            const int c = (tid & 1) * 32;
            const float4* kp = reinterpret_cast<const float4*>(
                Kb + (size_t)(k0 + r) * NH + c);
            const float4* vp = reinterpret_cast<const float4*>(
                Vb + (size_t)(k0 + r) * NH + c);
#pragma unroll
            for (int u = 0; u < 8; ++u) {
                *reinterpret_cast<uint4*>(&Ks[r * KS_S + c + u * 4]) = f4tf(kp[u]);
                *reinterpret_cast<uint4*>(&Vs[r * VS_S + c + u * 4]) = f4tf(vp[u]);
            }
        }
        __syncthreads();

        // ---- S = Q K^T ----
        float s[8][4];
#pragma unroll
        for (int nt = 0; nt < 8; ++nt)
#pragma unroll
            for (int r = 0; r < 4; ++r) s[nt][r] = 0.0f;

#pragma unroll
        for (int dc = 0; dc < 8; ++dc) {
            unsigned a0 = __float_as_uint(Qs[(w16 + g)     * QS_S + dc * 8 + t]);
            unsigned a1 = __float_as_uint(Qs[(w16 + g + 8) * QS_S + dc * 8 + t]);
            unsigned a2 = __float_as_uint(Qs[(w16 + g)     * QS_S + dc * 8 + t + 4]);
            unsigned a3 = __float_as_uint(Qs[(w16 + g + 8) * QS_S + dc * 8 + t + 4]);
#pragma unroll
            for (int nt = 0; nt < 8; ++nt) {
                unsigned b0 = __float_as_uint(Ks[(nt * 8 + g) * KS_S + dc * 8 + t]);
                unsigned b1 = __float_as_uint(Ks[(nt * 8 + g) * KS_S + dc * 8 + t + 4]);
                mma8(s[nt], a0, a1, a2, a3, b0, b1);
            }
        }

        // scale + causal mask (diagonal tile only)
        if (kt == qt) {
            const int rA = w16 + g, rB = w16 + g + 8;
#pragma unroll
            for (int nt = 0; nt < 8; ++nt) {
                const int c0 = nt * 8 + 2 * t, c1 = c0 + 1;
                s[nt][0] = (c0 <= rA) ? s[nt][0] * 0.125f : -1e30f;
                s[nt][1] = (c1 <= rA) ? s[nt][1] * 0.125f : -1e30f;
                s[nt][2] = (c0 <= rB) ? s[nt][2] * 0.125f : -1e30f;
                s[nt][3] = (c1 <= rB) ? s[nt][3] * 0.125f : -1e30f;
            }
        } else {
#pragma unroll
            for (int nt = 0; nt < 8; ++nt)
#pragma unroll
                for (int r = 0; r < 4; ++r) s[nt][r] *= 0.125f;
        }

        // ---- online softmax (rows g / g+8, reduced over the quad lanes) ----
        float cmA = -1e30f, cmB = -1e30f;
#pragma unroll
        for (int nt = 0; nt < 8; ++nt) {
            cmA = fmaxf(cmA, fmaxf(s[nt][0], s[nt][1]));
            cmB = fmaxf(cmB, fmaxf(s[nt][2], s[nt][3]));
        }
        cmA = fmaxf(cmA, __shfl_xor_sync(0xffffffffu, cmA, 1));
        cmA = fmaxf(cmA, __shfl_xor_sync(0xffffffffu, cmA, 2));
        cmB = fmaxf(cmB, __shfl_xor_sync(0xffffffffu, cmB, 1));
        cmB = fmaxf(cmB, __shfl_xor_sync(0xffffffffu, cmB, 2));

        const float mnA = fmaxf(mA, cmA);
        const float mnB = fmaxf(mB, cmB);
        const float cA  = __expf(mA - mnA);   // 0 on first tile
        const float cB  = __expf(mB - mnB);
        mA = mnA; mB = mnB;
        lA *= cA; lB *= cB;
#pragma unroll
        for (int nt = 0; nt < 8; ++nt) {
            o[nt][0] *= cA; o[nt][1] *= cA;
            o[nt][2] *= cB; o[nt][3] *= cB;
        }
#pragma unroll
        for (int nt = 0; nt < 8; ++nt) {
            s[nt][0] = __expf(s[nt][0] - mnA);
            s[nt][1] = __expf(s[nt][1] - mnA);
            s[nt][2] = __expf(s[nt][2] - mnB);
            s[nt][3] = __expf(s[nt][3] - mnB);
            lA += s[nt][0] + s[nt][1];
            lB += s[nt][2] + s[nt][3];
        }

        // ---- P -> warp-private smem rows (tf32-rounded), re-fragment ----
#pragma unroll
        for (int nt = 0; nt < 8; ++nt) {
            *reinterpret_cast<uint2*>(&Ps[(w16 + g) * PS_S + nt * 8 + 2 * t]) =
                make_uint2(f2tf(s[nt][0]), f2tf(s[nt][1]));
            *reinterpret_cast<uint2*>(&Ps[(w16 + g + 8) * PS_S + nt * 8 + 2 * t]) =
                make_uint2(f2tf(s[nt][2]), f2tf(s[nt][3]));
        }
        __syncwarp();

        // ---- O += P V ----
#pragma unroll
        for (int kc = 0; kc < 8; ++kc) {
            unsigned a0 = __float_as_uint(Ps[(w16 + g)     * PS_S + kc * 8 + t]);
            unsigned a1 = __float_as_uint(Ps[(w16 + g + 8) * PS_S + kc * 8 + t]);
            unsigned a2 = __float_as_uint(Ps[(w16 + g)     * PS_S + kc * 8 + t + 4]);
            unsigned a3 = __float_as_uint(Ps[(w16 + g + 8) * PS_S + kc * 8 + t + 4]);
#pragma unroll
            for (int nt = 0; nt < 8; ++nt) {
                unsigned b0 = __float_as_uint(Vs[(kc * 8 + t)     * VS_S + nt * 8 + g]);
                unsigned b1 = __float_as_uint(Vs[(kc * 8 + t + 4) * VS_S + nt * 8 + g]);
                mma8(o[nt], a0, a1, a2, a3, b0, b1);
            }
        }
        __syncwarp();   // P reads done before next iter's P writes
    }

    // finalize
    lA += __shfl_xor_sync(0xffffffffu, lA, 1);
    lA += __shfl_xor_sync(0xffffffffu, lA, 2);
    lB += __shfl_xor_sync(0xffffffffu, lB, 1);
    lB += __shfl_xor_sync(0xffffffffu, lB, 2);
    const float iA = 1.0f / lA;
    const float iB = 1.0f / lB;

    float* op = out + ((size_t)b * NS + q0) * NH;
#pragma unroll
    for (int nt = 0; nt < 8; ++nt) {
        *reinterpret_cast<float2*>(op + (size_t)(w16 + g) * NH + nt * 8 + 2 * t) =
            make_float2(o[nt][0] * iA, o[nt][1] * iA);
        *reinterpret_cast<float2*>(op + (size_t)(w16 + g + 8) * NH + nt * 8 + 2 * t) =
            make_float2(o[nt][2] * iB, o[nt][3] * iB);
    }
}

// ---------------------------------------------------------------------------
extern "C" void kernel_launch(void* const* d_in, const int* in_sizes, int n_in,
                              void* d_out, int out_size)
{
    const float* X  = (const float*)d_in[0];
    const float* Wq = (const float*)d_in[1];
    const float* Wk = (const float*)d_in[2];
    const float* Wv = (const float*)d_in[3];
    float* out = (float*)d_out;

    const int attn_smem = (3 * 64 * 68 + 64 * 72) * (int)sizeof(float); // 70656 B
    cudaFuncSetAttribute(attn_kernel,
                         cudaFuncAttributeMaxDynamicSharedMemorySize, attn_smem);

    proj_kernel<<<dim3((NB * NS) / 128, 1, 3), 128>>>(X, Wq, Wk, Wv);
    attn_kernel<<<dim3(NS / 64, NB), 128, attn_smem>>>(out);
}

// round 8
// speedup vs baseline: 5.2200x; 1.5219x over previous
#include <cuda_runtime.h>

#define NB 8
#define NS 2048
#define ND 768
#define NH 64
#define NQT 32            // q-tiles of 64
#define SKA 68            // smem row stride (floats), 68 % 32 == 4 -> conflict-free LDSM

__device__ float g_Q[NB * NS * NH];
__device__ float g_K[NB * NS * NH];
__device__ float g_V[NB * NS * NH];

// split-K partials: [half][b][qt] -> 64x64 unnormalized O, plus per-row m,l
__device__ float g_Op[2 * NB * NQT * 64 * 64];
__device__ float g_M[2 * NB * NQT * 64];
__device__ float g_L[2 * NB * NQT * 64];

// ---------------------------------------------------------------------------
// helpers
// ---------------------------------------------------------------------------
__device__ __forceinline__ unsigned f2tf(float f) {
    unsigned u;
    asm("cvt.rna.tf32.f32 %0, %1;" : "=r"(u) : "f"(f));
    return u;
}
__device__ __forceinline__ uint4 f4tf(float4 v) {
    uint4 r;
    r.x = f2tf(v.x); r.y = f2tf(v.y); r.z = f2tf(v.z); r.w = f2tf(v.w);
    return r;
}
__device__ __forceinline__ void mma8(float c[4],
                                     unsigned a0, unsigned a1, unsigned a2, unsigned a3,
                                     unsigned b0, unsigned b1) {
    asm("mma.sync.aligned.m16n8k8.row.col.f32.tf32.tf32.f32 "
        "{%0,%1,%2,%3}, {%4,%5,%6,%7}, {%8,%9}, {%0,%1,%2,%3};"
        : "+f"(c[0]), "+f"(c[1]), "+f"(c[2]), "+f"(c[3])
        : "r"(a0), "r"(a1), "r"(a2), "r"(a3), "r"(b0), "r"(b1));
}
__device__ __forceinline__ void ldsm4(unsigned &r0, unsigned &r1,
                                      unsigned &r2, unsigned &r3, unsigned addr) {
    asm volatile("ldmatrix.sync.aligned.m8n8.x4.shared.b16 {%0,%1,%2,%3}, [%4];"
                 : "=r"(r0), "=r"(r1), "=r"(r2), "=r"(r3) : "r"(addr));
}

// ---------------------------------------------------------------------------
// Kernel 1: QKV projection via tf32 mma (unchanged from R6).
// ---------------------------------------------------------------------------
#define XS_S 36
#define WS_S 72

__global__ __launch_bounds__(128, 3) void proj_kernel(
    const float* __restrict__ X,
    const float* __restrict__ Wq,
    const float* __restrict__ Wk,
    const float* __restrict__ Wv)
{
    const int z = blockIdx.z;
    const float* __restrict__ W   = (z == 0) ? Wq : (z == 1) ? Wk : Wv;
    float* __restrict__       Out = (z == 0) ? g_Q : (z == 1) ? g_K : g_V;

    __shared__ float Xs[128 * XS_S];
    __shared__ float Ws[32 * WS_S];

    const int row0 = blockIdx.x * 128;
    const int tid  = threadIdx.x;
    const int wrp  = tid >> 5;
    const int lane = tid & 31;
    const int g    = lane >> 2;
    const int t    = lane & 3;
    const int mrow = wrp * 32;

    float acc[2][8][4];
#pragma unroll
    for (int mt = 0; mt < 2; ++mt)
#pragma unroll
        for (int nt = 0; nt < 8; ++nt)
#pragma unroll
            for (int r = 0; r < 4; ++r) acc[mt][nt][r] = 0.0f;

    const int xr = tid >> 3;
    const int xc = (tid & 7) * 4;
    const int wr = tid >> 4;
    const int wc = (tid & 15) * 4;

    for (int kk = 0; kk < ND; kk += 32) {
#pragma unroll
        for (int it = 0; it < 8; ++it) {
            const int r = xr + it * 16;
            float4 v = *reinterpret_cast<const float4*>(
                X + (size_t)(row0 + r) * ND + kk + xc);
            *reinterpret_cast<uint4*>(&Xs[r * XS_S + xc]) = f4tf(v);
        }
#pragma unroll
        for (int it = 0; it < 4; ++it) {
            const int r = wr + it * 8;
            float4 v = *reinterpret_cast<const float4*>(
                W + (size_t)(kk + r) * NH + wc);
            *reinterpret_cast<uint4*>(&Ws[r * WS_S + wc]) = f4tf(v);
        }
        __syncthreads();

#pragma unroll
        for (int dc = 0; dc < 4; ++dc) {
            unsigned a[2][4];
#pragma unroll
            for (int mt = 0; mt < 2; ++mt) {
                const int rb = mrow + mt * 16;
                a[mt][0] = __float_as_uint(Xs[(rb + g)     * XS_S + dc * 8 + t]);
                a[mt][1] = __float_as_uint(Xs[(rb + g + 8) * XS_S + dc * 8 + t]);
                a[mt][2] = __float_as_uint(Xs[(rb + g)     * XS_S + dc * 8 + t + 4]);
                a[mt][3] = __float_as_uint(Xs[(rb + g + 8) * XS_S + dc * 8 + t + 4]);
            }
#pragma unroll
            for (int nt = 0; nt < 8; ++nt) {
                unsigned b0 = __float_as_uint(Ws[(dc * 8 + t)     * WS_S + nt * 8 + g]);
                unsigned b1 = __float_as_uint(Ws[(dc * 8 + t + 4) * WS_S + nt * 8 + g]);
                mma8(acc[0][nt], a[0][0], a[0][1], a[0][2], a[0][3], b0, b1);
                mma8(acc[1][nt], a[1][0], a[1][1], a[1][2], a[1][3], b0, b1);
            }
        }
        __syncthreads();
    }

#pragma unroll
    for (int mt = 0; mt < 2; ++mt) {
        const int rb = row0 + mrow + mt * 16;
#pragma unroll
        for (int nt = 0; nt < 8; ++nt) {
            *reinterpret_cast<float2*>(
                Out + (size_t)(rb + g) * NH + nt * 8 + 2 * t) =
                make_float2(acc[mt][nt][0], acc[mt][nt][1]);
            *reinterpret_cast<float2*>(
                Out + (size_t)(rb + g + 8) * NH + nt * 8 + 2 * t) =
                make_float2(acc[mt][nt][2], acc[mt][nt][3]);
        }
    }
}

// ---------------------------------------------------------------------------
// Kernel 2: causal flash attention, tf32 mma + ldmatrix operands + split-K x2.
// grid (32, NB, 2): qt = 31-bx (long first), half = bz over k-tile range.
// Block: 128 threads / 4 warps, warp w owns q rows [w*16, w*16+16).
// smem: Qs | Ks | Ps | Vt, each 64 x 68 (stride 68 => LDSM conflict-free).
// Writes unnormalized partial O + per-row (m, l) to global scratch.
// ---------------------------------------------------------------------------
__global__ __launch_bounds__(128, 3) void attn_kernel()
{
    extern __shared__ float sm[];
    float* __restrict__ Qs = sm;                 // [64][68]  Q rows (tf32 bits)
    float* __restrict__ Ks = sm + 64 * SKA;      // [64][68]  K rows
    float* __restrict__ Ps = sm + 2 * 64 * SKA;  // [64][68]  P rows (warp-private)
    float* __restrict__ Vt = sm + 3 * 64 * SKA;  // [64][68]  V transposed [h][k]

    const int b    = blockIdx.y;
    const int qt   = (NQT - 1) - blockIdx.x;
    const int half = blockIdx.z;
    const int q0   = qt * 64;
    const int tid  = threadIdx.x;
    const int wrp  = tid >> 5;
    const int lane = tid & 31;
    const int g    = lane >> 2;
    const int t    = lane & 3;
    const int w16  = wrp * 16;

    const int T  = qt + 1;                 // causal k-tiles for this q-tile
    const int h0 = (T + 1) >> 1;
    const int tb = half ? h0 : 0;
    const int te = half ? T  : h0;

    const float* __restrict__ Qb = g_Q + (size_t)b * NS * NH;
    const float* __restrict__ Kb = g_K + (size_t)b * NS * NH;
    const float* __restrict__ Vb = g_V + (size_t)b * NS * NH;

    // ---- ldmatrix per-lane addresses (byte offsets in shared space) ----
    const unsigned smb = (unsigned)__cvta_generic_to_shared(sm);
    const int rowA = w16 + (lane & 15);
    const int colA = (lane >> 4) * 4;
    const unsigned aQ = smb + (unsigned)((rowA * SKA + colA) * 4);
    const unsigned aP = aQ + 2u * 64 * SKA * 4;
    const int rowB = (lane & 7) | ((lane >> 1) & 8);
    const int colB = ((lane >> 3) & 1) * 4;
    const unsigned bK = smb + 1u * 64 * SKA * 4 + (unsigned)((rowB * SKA + colB) * 4);
    const unsigned bV = smb + 3u * 64 * SKA * 4 + (unsigned)((rowB * SKA + colB) * 4);

    // ---- Q tile -> smem (tf32-rounded) ----
    {
        const int r = tid >> 1;
        const int c = (tid & 1) * 32;
        const float4* qp = reinterpret_cast<const float4*>(
            Qb + (size_t)(q0 + r) * NH + c);
#pragma unroll
        for (int u = 0; u < 8; ++u)
            *reinterpret_cast<uint4*>(&Qs[r * SKA + c + u * 4]) = f4tf(qp[u]);
    }

    float o[8][4];
#pragma unroll
    for (int nt = 0; nt < 8; ++nt)
#pragma unroll
        for (int r = 0; r < 4; ++r) o[nt][r] = 0.0f;
    float mA = -1e30f, mB = -1e30f;
    float lA = 0.0f,   lB = 0.0f;

    for (int kt = tb; kt < te; ++kt) {
        const int k0 = kt * 64;

        __syncthreads();   // prev iter done reading Ks/Vt (also orders Q stores)
        // K natural rows
        {
            const int r = tid >> 1;
            const int c = (tid & 1) * 32;
            const float4* kp = reinterpret_cast<const float4*>(
                Kb + (size_t)(k0 + r) * NH + c);
#pragma unroll
            for (int u = 0; u < 8; ++u)
                *reinterpret_cast<uint4*>(&Ks[r * SKA + c + u * 4]) = f4tf(kp[u]);
        }
        // V transposed: Vt[h][k]
        {
            const int rv = tid & 63;
            const int hb = (tid >> 6) * 32;
            const float4* vp = reinterpret_cast<const float4*>(
                Vb + (size_t)(k0 + rv) * NH + hb);
#pragma unroll
            for (int u = 0; u < 8; ++u) {
                float4 v = vp[u];
                const int h = hb + u * 4;
                Vt[(h + 0) * SKA + rv] = __uint_as_float(f2tf(v.x));
                Vt[(h + 1) * SKA + rv] = __uint_as_float(f2tf(v.y));
                Vt[(h + 2) * SKA + rv] = __uint_as_float(f2tf(v.z));
                Vt[(h + 3) * SKA + rv] = __uint_as_float(f2tf(v.w));
            }
        }
        __syncthreads();

        // ---- S = Q K^T ----
        float s[8][4];
#pragma unroll
        for (int nt = 0; nt < 8; ++nt)
#pragma unroll
            for (int r = 0; r < 4; ++r) s[nt][r] = 0.0f;

#pragma unroll
        for (int dc = 0; dc < 8; ++dc) {
            unsigned a0, a1, a2, a3;
            ldsm4(a0, a1, a2, a3, aQ + dc * 32);
#pragma unroll
            for (int p = 0; p < 4; ++p) {
                unsigned b0, b1, b2, b3;
                ldsm4(b0, b1, b2, b3, bK + p * (16 * SKA * 4) + dc * 32);
                mma8(s[2 * p],     a0, a1, a2, a3, b0, b1);
                mma8(s[2 * p + 1], a0, a1, a2, a3, b2, b3);
            }
        }

        // scale + causal mask (diagonal tile only)
        if (kt == qt) {
            const int rA = w16 + g, rB = w16 + g + 8;
#pragma unroll
            for (int nt = 0; nt < 8; ++nt) {
                const int c0 = nt * 8 + 2 * t, c1 = c0 + 1;
                s[nt][0] = (c0 <= rA) ? s[nt][0] * 0.125f : -1e30f;
                s[nt][1] = (c1 <= rA) ? s[nt][1] * 0.125f : -1e30f;
                s[nt][2] = (c0 <= rB) ? s[nt][2] * 0.125f : -1e30f;
                s[nt][3] = (c1 <= rB) ? s[nt][3] * 0.125f : -1e30f;
            }
        } else {
#pragma unroll
            for (int nt = 0; nt < 8; ++nt)
#pragma unroll
                for (int r = 0; r < 4; ++r) s[nt][r] *= 0.125f;
        }

        // ---- online softmax ----
        float cmA = -1e30f, cmB = -1e30f;
#pragma unroll
        for (int nt = 0; nt < 8; ++nt) {
            cmA = fmaxf(cmA, fmaxf(s[nt][0], s[nt][1]));
            cmB = fmaxf(cmB, fmaxf(s[nt][2], s[nt][3]));
        }
        cmA = fmaxf(cmA, __shfl_xor_sync(0xffffffffu, cmA, 1));
        cmA = fmaxf(cmA, __shfl_xor_sync(0xffffffffu, cmA, 2));
        cmB = fmaxf(cmB, __shfl_xor_sync(0xffffffffu, cmB, 1));
        cmB = fmaxf(cmB, __shfl_xor_sync(0xffffffffu, cmB, 2));

        const float mnA = fmaxf(mA, cmA);
        const float mnB = fmaxf(mB, cmB);
        const float cA  = __expf(mA - mnA);
        const float cB  = __expf(mB - mnB);
        mA = mnA; mB = mnB;
        lA *= cA; lB *= cB;
#pragma unroll
        for (int nt = 0; nt < 8; ++nt) {
            o[nt][0] *= cA; o[nt][1] *= cA;
            o[nt][2] *= cB; o[nt][3] *= cB;
        }
#pragma unroll
        for (int nt = 0; nt < 8; ++nt) {
            s[nt][0] = __expf(s[nt][0] - mnA);
            s[nt][1] = __expf(s[nt][1] - mnA);
            s[nt][2] = __expf(s[nt][2] - mnB);
            s[nt][3] = __expf(s[nt][3] - mnB);
            lA += s[nt][0] + s[nt][1];
            lB += s[nt][2] + s[nt][3];
        }

        // ---- P -> warp-private smem rows (tf32), re-fragment via ldmatrix ----
#pragma unroll
        for (int nt = 0; nt < 8; ++nt) {
            *reinterpret_cast<uint2*>(&Ps[(w16 + g) * SKA + nt * 8 + 2 * t]) =
                make_uint2(f2tf(s[nt][0]), f2tf(s[nt][1]));
            *reinterpret_cast<uint2*>(&Ps[(w16 + g + 8) * SKA + nt * 8 + 2 * t]) =
                make_uint2(f2tf(s[nt][2]), f2tf(s[nt][3]));
        }
        __syncwarp();

        // ---- O += P V ----
#pragma unroll
        for (int kc = 0; kc < 8; ++kc) {
            unsigned a0, a1, a2, a3;
            ldsm4(a0, a1, a2, a3, aP + kc * 32);
#pragma unroll
            for (int p = 0; p < 4; ++p) {
                unsigned b0, b1, b2, b3;
                ldsm4(b0, b1, b2, b3, bV + p * (16 * SKA * 4) + kc * 32);
                mma8(o[2 * p],     a0, a1, a2, a3, b0, b1);
                mma8(o[2 * p + 1], a0, a1, a2, a3, b2, b3);
            }
        }
        __syncwarp();   // P reads done before next iteration's P writes
    }

    // ---- store partials (unnormalized O, per-row m and l) ----
    lA += __shfl_xor_sync(0xffffffffu, lA, 1);
    lA += __shfl_xor_sync(0xffffffffu, lA, 2);
    lB += __shfl_xor_sync(0xffffffffu, lB, 1);
    lB += __shfl_xor_sync(0xffffffffu, lB, 2);

    const size_t slot = ((size_t)half * NB + b) * NQT + qt;
    float* op = g_Op + slot * 64 * 64;
#pragma unroll
    for (int nt = 0; nt < 8; ++nt) {
        *reinterpret_cast<float2*>(op + (w16 + g) * 64 + nt * 8 + 2 * t) =
            make_float2(o[nt][0], o[nt][1]);
        *reinterpret_cast<float2*>(op + (w16 + g + 8) * 64 + nt * 8 + 2 * t) =
            make_float2(o[nt][2], o[nt][3]);
    }
    if (t == 0) {
        g_M[slot * 64 + w16 + g]     = mA;
        g_M[slot * 64 + w16 + g + 8] = mB;
        g_L[slot * 64 + w16 + g]     = lA;
        g_L[slot * 64 + w16 + g + 8] = lB;
    }
}

// ---------------------------------------------------------------------------
// Kernel 3: merge split-K partials. grid (32, NB), 256 threads.
// ---------------------------------------------------------------------------
__global__ __launch_bounds__(256) void merge_kernel(float* __restrict__ out)
{
    const int qt  = blockIdx.x;
    const int b   = blockIdx.y;
    const int tid = threadIdx.x;
    const int r   = tid >> 2;
    const int cs  = (tid & 3) * 16;

    const size_t s0 = ((size_t)0 * NB + b) * NQT + qt;
    const size_t s1 = ((size_t)1 * NB + b) * NQT + qt;

    const float m0 = g_M[s0 * 64 + r];
    const float m1 = g_M[s1 * 64 + r];
    const float l0 = g_L[s0 * 64 + r];
    const float l1 = g_L[s1 * 64 + r];

    const float M  = fmaxf(m0, m1);
    float f0 = __expf(m0 - M);
    float f1 = __expf(m1 - M);
    const float inv = 1.0f / (l0 * f0 + l1 * f1);
    f0 *= inv; f1 *= inv;

    const float4* p0 = reinterpret_cast<const float4*>(g_Op + s0 * 4096 + r * 64 + cs);
    const float4* p1 = reinterpret_cast<const float4*>(g_Op + s1 * 4096 + r * 64 + cs);
    float4* po = reinterpret_cast<float4*>(
        out + ((size_t)b * NS + qt * 64 + r) * NH + cs);

#pragma unroll
    for (int u = 0; u < 4; ++u) {
        float4 a = p0[u], c = p1[u];
        po[u] = make_float4(a.x * f0 + c.x * f1, a.y * f0 + c.y * f1,
                            a.z * f0 + c.z * f1, a.w * f0 + c.w * f1);
    }
}

// ---------------------------------------------------------------------------
extern "C" void kernel_launch(void* const* d_in, const int* in_sizes, int n_in,
                              void* d_out, int out_size)
{
    const float* X  = (const float*)d_in[0];
    const float* Wq = (const float*)d_in[1];
    const float* Wk = (const float*)d_in[2];
    const float* Wv = (const float*)d_in[3];
    float* out = (float*)d_out;

    const int attn_smem = 4 * 64 * SKA * (int)sizeof(float);   // 69632 B
    cudaFuncSetAttribute(attn_kernel,
                         cudaFuncAttributeMaxDynamicSharedMemorySize, attn_smem);

    proj_kernel<<<dim3((NB * NS) / 128, 1, 3), 128>>>(X, Wq, Wk, Wv);
    attn_kernel<<<dim3(NQT, NB, 2), 128, attn_smem>>>();
    merge_kernel<<<dim3(NQT, NB), 256>>>(out);
}